// round 2
// baseline (speedup 1.0000x reference)
#include <cuda_runtime.h>
#include <cuda_bf16.h>
#include <math.h>
#include <stdint.h>

#define Nn 4096
#define Ff 512
#define Dd 64
#define Hh 8
#define HD 512   // Hh*Dd
#define Cc 40
#define MAXDEG 128

// ---------------- scratch (static device globals; no allocation) -------------
__device__ int   g_adj_mode;            // 0=u8, 1=i32, 2=f32, 3=bf16, 4=f64
__device__ int   g_deg[Nn];
__device__ int   g_nbr[Nn * MAXDEG];
__device__ float g_Bpack[Ff * HD];      // W1 repacked to [F][H*D]
__device__ float g_h[(size_t)Nn * HD];  // layer1 features, [n][h*D+d]
__device__ float g_si[Hh * Nn];
__device__ float g_sj[Hh * Nn];
__device__ float g_x2[(size_t)Nn * HD];
__device__ float g_h2[Nn * Cc];
__device__ float g_s2i[Nn];
__device__ float g_s2j[Nn];

// ---------------- adj dtype detection ---------------------------------------
// adj[i][i] == 1 guaranteed (self loops). Probe adj[1][1] under each layout.
__global__ void k_detect(const unsigned char* adj) {
    int mode;
    if (adj[(size_t)Nn + 1] == 1) {
        mode = 0;                                            // u8/bool
    } else if (((const uint16_t*)adj)[(size_t)Nn + 1] == 0x3F80u) {
        mode = 3;                                            // bf16
    } else {
        uint32_t v32 = ((const uint32_t*)adj)[(size_t)Nn + 1];
        if (v32 == 0x3F800000u) mode = 2;                    // f32
        else if (((const uint64_t*)adj)[(size_t)Nn + 1] == 0x3FF0000000000000ull) mode = 4; // f64
        else mode = 1;                                       // i32
    }
    g_adj_mode = mode;
}

// ---------------- build neighbor lists (1 warp per row, order-preserving) ----
__global__ __launch_bounds__(256) void k_build(const unsigned char* adj) {
    int row  = blockIdx.x * 8 + (threadIdx.x >> 5);
    int lane = threadIdx.x & 31;
    int mode = g_adj_mode;
    const unsigned char* r8  = adj + (size_t)row * Nn;
    const int*           r32 = (const int*)adj + (size_t)row * Nn;
    const float*         rf  = (const float*)adj + (size_t)row * Nn;
    const uint16_t*      rb  = (const uint16_t*)adj + (size_t)row * Nn;
    const double*        rd  = (const double*)adj + (size_t)row * Nn;
    int cnt = 0;
    for (int base = 0; base < Nn; base += 32) {
        int j = base + lane;
        bool edge;
        if (mode == 0)      edge = r8[j]  != 0;
        else if (mode == 1) edge = r32[j] != 0;
        else if (mode == 2) edge = rf[j]  != 0.0f;
        else if (mode == 3) edge = rb[j]  != 0;
        else                edge = rd[j]  != 0.0;
        unsigned m = __ballot_sync(0xffffffffu, edge);
        if (edge) {
            int pos = cnt + __popc(m & ((1u << lane) - 1u));
            if (pos < MAXDEG) g_nbr[row * MAXDEG + pos] = j;
        }
        cnt += __popc(m);
    }
    if (lane == 0) g_deg[row] = (cnt < MAXDEG) ? cnt : MAXDEG;
}

// ---------------- pack W1 [H,F,D] -> Bpack [F, H*D] --------------------------
__global__ void k_pack(const float* __restrict__ W1) {
    int idx = blockIdx.x * 256 + threadIdx.x;    // over H*F*D = 262144
    int d = idx % Dd;
    int f = (idx / Dd) % Ff;
    int h = idx / (Dd * Ff);
    g_Bpack[(size_t)f * HD + h * Dd + d] = W1[idx];
}

// ---------------- fp32 GEMM: C[M,Nc] = A[M,K] @ B[K,Nc]; tile 128x64 ---------
__global__ __launch_bounds__(256) void k_gemm128x64(
    const float* __restrict__ A, const float* __restrict__ B,
    float* __restrict__ Cm, int M, int K, int Nc)
{
    __shared__ float As[16][128];
    __shared__ float Bs[16][64];
    int t   = threadIdx.x;
    int row0 = blockIdx.y * 128;
    int col0 = blockIdx.x * 64;
    int tx = t & 15;   // col group (4 cols each)
    int ty = t >> 4;   // row group (8 rows each)
    float acc[8][4];
    #pragma unroll
    for (int i = 0; i < 8; i++)
        #pragma unroll
        for (int j = 0; j < 4; j++) acc[i][j] = 0.f;

    for (int k0 = 0; k0 < K; k0 += 16) {
        #pragma unroll
        for (int s = 0; s < 2; s++) {
            int slot = t + s * 256;       // 0..511
            int ar   = slot >> 2;         // 0..127
            int ac4  = slot & 3;          // 0..3
            float4 v = *(const float4*)&A[(size_t)(row0 + ar) * K + k0 + ac4 * 4];
            As[ac4 * 4 + 0][ar] = v.x;
            As[ac4 * 4 + 1][ar] = v.y;
            As[ac4 * 4 + 2][ar] = v.z;
            As[ac4 * 4 + 3][ar] = v.w;
        }
        {
            int br  = t >> 4;             // 0..15
            int bc4 = t & 15;             // 0..15
            float4 v = *(const float4*)&B[(size_t)(k0 + br) * Nc + col0 + bc4 * 4];
            *(float4*)&Bs[br][bc4 * 4] = v;
        }
        __syncthreads();
        #pragma unroll
        for (int k = 0; k < 16; k++) {
            float a[8], b[4];
            #pragma unroll
            for (int i = 0; i < 8; i++) a[i] = As[k][ty * 8 + i];
            #pragma unroll
            for (int j = 0; j < 4; j++) b[j] = Bs[k][tx * 4 + j];
            #pragma unroll
            for (int i = 0; i < 8; i++)
                #pragma unroll
                for (int j = 0; j < 4; j++) acc[i][j] += a[i] * b[j];
        }
        __syncthreads();
    }
    #pragma unroll
    for (int i = 0; i < 8; i++)
        #pragma unroll
        for (int j = 0; j < 4; j++)
            Cm[(size_t)(row0 + ty * 8 + i) * Nc + col0 + tx * 4 + j] = acc[i][j];
}

// ---------------- si/sj: per (n,h) dot with attention vectors ----------------
__global__ __launch_bounds__(256) void k_sisj(
    const float* __restrict__ a1_src, const float* __restrict__ a1_dst)
{
    __shared__ float ssrc[HD], sdst[HD];
    for (int i = threadIdx.x; i < HD; i += 256) { ssrc[i] = a1_src[i]; sdst[i] = a1_dst[i]; }
    __syncthreads();
    int t = threadIdx.x;
    int h = t & 7;
    int n = blockIdx.x * 32 + (t >> 3);
    const float* hp = &g_h[(size_t)n * HD + h * Dd];
    float si = 0.f, sj = 0.f;
    #pragma unroll 8
    for (int d = 0; d < Dd; d++) {
        float v = hp[d];
        si += v * sdst[h * Dd + d];
        sj += v * ssrc[h * Dd + d];
    }
    g_si[h * Nn + n] = si;
    g_sj[h * Nn + n] = sj;
}

// ---------------- layer-1 sparse attention + aggregate + ELU -----------------
__global__ __launch_bounds__(256) void k_layer1() {
    __shared__ int   nbr_sh[MAXDEG];
    __shared__ float w_sh[Hh][MAXDEG];
    int i = blockIdx.x;
    int deg = g_deg[i];
    int t = threadIdx.x, lane = t & 31, wid = t >> 5;
    for (int jj = t; jj < deg; jj += 256) nbr_sh[jj] = g_nbr[i * MAXDEG + jj];
    __syncthreads();

    // warp `wid` handles head `wid`: masked softmax over neighbors
    {
        int h = wid;
        float sii = g_si[h * Nn + i];
        float ev[4];
        float m = -1e30f;
        #pragma unroll
        for (int it = 0; it < 4; it++) {
            int jj = it * 32 + lane;
            float e = -1e30f;
            if (jj < deg) {
                float x = sii + g_sj[h * Nn + nbr_sh[jj]];
                e = (x >= 0.f) ? x : 0.2f * x;   // leaky relu
            }
            ev[it] = e;
            m = fmaxf(m, e);
        }
        #pragma unroll
        for (int o = 16; o; o >>= 1) m = fmaxf(m, __shfl_xor_sync(0xffffffffu, m, o));
        float s = 0.f;
        #pragma unroll
        for (int it = 0; it < 4; it++) {
            int jj = it * 32 + lane;
            float w = (jj < deg) ? expf(ev[it] - m) : 0.f;
            ev[it] = w;
            s += w;
        }
        #pragma unroll
        for (int o = 16; o; o >>= 1) s += __shfl_xor_sync(0xffffffffu, s, o);
        float inv = 1.f / s;
        #pragma unroll
        for (int it = 0; it < 4; it++) {
            int jj = it * 32 + lane;
            if (jj < deg) w_sh[h][jj] = ev[it] * inv;
        }
    }
    __syncthreads();

    // aggregate: 512 dims over 256 threads x 2
    #pragma unroll
    for (int rep = 0; rep < 2; rep++) {
        int dim = t + rep * 256;
        int h = dim >> 6;
        float acc = 0.f;
        for (int jj = 0; jj < deg; jj++)
            acc += w_sh[h][jj] * g_h[(size_t)nbr_sh[jj] * HD + dim];
        g_x2[(size_t)i * HD + dim] = (acc > 0.f) ? acc : expm1f(acc);  // ELU
    }
}

// ---------------- output head: h2 = x2 @ W2, fused s2i/s2j -------------------
__global__ __launch_bounds__(64) void k_out_head(
    const float* __restrict__ W2, const float* __restrict__ a2_src,
    const float* __restrict__ a2_dst)
{
    __shared__ float xrow[HD];
    __shared__ float h2row[Cc];
    int i = blockIdx.x, t = threadIdx.x;
    for (int k = t; k < HD; k += 64) xrow[k] = g_x2[(size_t)i * HD + k];
    __syncthreads();
    if (t < Cc) {
        float acc = 0.f;
        #pragma unroll 8
        for (int k = 0; k < HD; k++) acc += xrow[k] * W2[k * Cc + t];
        h2row[t] = acc;
        g_h2[i * Cc + t] = acc;
    }
    __syncthreads();
    if (t < 32) {
        float pi = h2row[t] * a2_dst[t];
        float pj = h2row[t] * a2_src[t];
        if (t < 8) {
            pi += h2row[t + 32] * a2_dst[t + 32];
            pj += h2row[t + 32] * a2_src[t + 32];
        }
        #pragma unroll
        for (int o = 16; o; o >>= 1) {
            pi += __shfl_xor_sync(0xffffffffu, pi, o);
            pj += __shfl_xor_sync(0xffffffffu, pj, o);
        }
        if (t == 0) { g_s2i[i] = pi; g_s2j[i] = pj; }
    }
}

// ---------------- layer-2 sparse attention -> final output -------------------
__global__ __launch_bounds__(64) void k_layer2(float* __restrict__ out) {
    __shared__ int   nbr_sh[MAXDEG];
    __shared__ float w_sh[MAXDEG];
    int i = blockIdx.x, t = threadIdx.x, lane = t & 31;
    int deg = g_deg[i];
    for (int jj = t; jj < deg; jj += 64) nbr_sh[jj] = g_nbr[i * MAXDEG + jj];
    __syncthreads();
    if (t < 32) {
        float sii = g_s2i[i];
        float ev[4];
        float m = -1e30f;
        #pragma unroll
        for (int it = 0; it < 4; it++) {
            int jj = it * 32 + lane;
            float e = -1e30f;
            if (jj < deg) {
                float x = sii + g_s2j[nbr_sh[jj]];
                e = (x >= 0.f) ? x : 0.2f * x;
            }
            ev[it] = e;
            m = fmaxf(m, e);
        }
        #pragma unroll
        for (int o = 16; o; o >>= 1) m = fmaxf(m, __shfl_xor_sync(0xffffffffu, m, o));
        float s = 0.f;
        #pragma unroll
        for (int it = 0; it < 4; it++) {
            int jj = it * 32 + lane;
            float w = (jj < deg) ? expf(ev[it] - m) : 0.f;
            ev[it] = w;
            s += w;
        }
        #pragma unroll
        for (int o = 16; o; o >>= 1) s += __shfl_xor_sync(0xffffffffu, s, o);
        float inv = 1.f / s;
        #pragma unroll
        for (int it = 0; it < 4; it++) {
            int jj = it * 32 + lane;
            if (jj < deg) w_sh[jj] = ev[it] * inv;
        }
    }
    __syncthreads();
    if (t < Cc) {
        float acc = 0.f;
        for (int jj = 0; jj < deg; jj++)
            acc += w_sh[jj] * g_h2[nbr_sh[jj] * Cc + t];
        out[(size_t)i * Cc + t] = acc;
    }
}

// ---------------- launch -----------------------------------------------------
extern "C" void kernel_launch(void* const* d_in, const int* in_sizes, int n_in,
                              void* d_out, int out_size) {
    const float*         x      = (const float*)d_in[0];
    const unsigned char* adj    = (const unsigned char*)d_in[1];
    const float*         W1     = (const float*)d_in[2];
    const float*         a1_src = (const float*)d_in[3];
    const float*         a1_dst = (const float*)d_in[4];
    const float*         W2     = (const float*)d_in[5];
    const float*         a2_src = (const float*)d_in[6];
    const float*         a2_dst = (const float*)d_in[7];
    float* out = (float*)d_out;

    // resolve scratch symbol addresses (host side; no allocation)
    static float* h_ptr = nullptr;
    static float* bpack_ptr = nullptr;
    if (!h_ptr) {
        cudaGetSymbolAddress((void**)&h_ptr, g_h);
        cudaGetSymbolAddress((void**)&bpack_ptr, g_Bpack);
    }

    k_detect<<<1, 1>>>(adj);
    k_build<<<Nn / 8, 256>>>(adj);
    k_pack<<<(Hh * Ff * Dd) / 256, 256>>>(W1);
    k_gemm128x64<<<dim3(HD / 64, Nn / 128), 256>>>(x, bpack_ptr, h_ptr, Nn, Ff, HD);
    k_sisj<<<Nn / 32, 256>>>(a1_src, a1_dst);
    k_layer1<<<Nn, 256>>>();
    k_out_head<<<Nn, 64>>>(W2, a2_src, a2_dst);
    k_layer2<<<Nn, 64>>>(out);
}

// round 3
// speedup vs baseline: 1.1861x; 1.1861x over previous
#include <cuda_runtime.h>
#include <cuda_bf16.h>
#include <math.h>
#include <stdint.h>

#define Nn 4096
#define Ff 512
#define Dd 64
#define Hh 8
#define HD 512   // Hh*Dd
#define Cc 40
#define C2 64    // padded class dim
#define MAXDEG 128

// ---------------- scratch (static device globals; no allocation) -------------
__device__ int   g_deg[Nn];
__device__ int   g_nbr[Nn * MAXDEG];
__device__ float g_Bpack[Ff * HD];         // W1 repacked to [F][H*D]
__device__ float g_W2pad[Ff * C2];         // W2 zero-padded to [512][64]
__device__ float g_h[(size_t)Nn * HD];     // layer1 features, [n][h*D+d]
__device__ float g_si[Hh * Nn];
__device__ float g_sj[Hh * Nn];
__device__ float g_x2[(size_t)Nn * HD];
__device__ float g_h2p[(size_t)Nn * C2];   // padded h2
__device__ float g_s2i[Nn];
__device__ float g_s2j[Nn];

// ---------------- adj dtype detection (device helper) ------------------------
__device__ __forceinline__ int detect_mode(const unsigned char* adj) {
    // adj[1][1] == 1 guaranteed (self loops)
    if (adj[(size_t)Nn + 1] == 1) return 0;                               // u8
    if (((const uint16_t*)adj)[(size_t)Nn + 1] == 0x3F80u) return 3;      // bf16
    uint32_t v32 = ((const uint32_t*)adj)[(size_t)Nn + 1];
    if (v32 == 0x3F800000u) return 2;                                     // f32
    if (((const uint64_t*)adj)[(size_t)Nn + 1] == 0x3FF0000000000000ull) return 4; // f64
    return 1;                                                             // i32
}

__device__ __forceinline__ unsigned nz4(unsigned w) {
    unsigned c = 0;
    if (w & 0x000000FFu) c |= 1u;
    if (w & 0x0000FF00u) c |= 2u;
    if (w & 0x00FF0000u) c |= 4u;
    if (w & 0xFF000000u) c |= 8u;
    return c;
}

// ---------------- build neighbor lists (1 warp per row, order-preserving) ----
__global__ __launch_bounds__(256) void k_build(const unsigned char* adj) {
    int row  = blockIdx.x * 8 + (threadIdx.x >> 5);
    int lane = threadIdx.x & 31;
    int mode = detect_mode(adj);
    const unsigned FULL = 0xffffffffu;

    if (mode == 0) {
        // fast path: 16 bytes per lane per iteration (512 B per warp iter)
        const uint4* r = (const uint4*)(adj + (size_t)row * Nn);
        int cnt = 0;
        #pragma unroll
        for (int it = 0; it < Nn / 512; it++) {
            uint4 v = r[it * 32 + lane];
            unsigned msk = nz4(v.x) | (nz4(v.y) << 4) | (nz4(v.z) << 8) | (nz4(v.w) << 12);
            int c = __popc(msk);
            // inclusive scan across lanes
            int pref = c;
            #pragma unroll
            for (int o = 1; o < 32; o <<= 1) {
                int n = __shfl_up_sync(FULL, pref, o);
                if (lane >= o) pref += n;
            }
            int base = cnt + pref - c;
            int j0 = it * 512 + lane * 16;
            int pos = base;
            while (msk) {
                int b = __ffs(msk) - 1;
                msk &= msk - 1;
                if (pos < MAXDEG) g_nbr[row * MAXDEG + pos] = j0 + b;
                pos++;
            }
            cnt += __shfl_sync(FULL, pref, 31);
        }
        if (lane == 0) g_deg[row] = (cnt < MAXDEG) ? cnt : MAXDEG;
    } else {
        // generic fallback
        const int*      r32 = (const int*)adj + (size_t)row * Nn;
        const float*    rf  = (const float*)adj + (size_t)row * Nn;
        const uint16_t* rb  = (const uint16_t*)adj + (size_t)row * Nn;
        const double*   rd  = (const double*)adj + (size_t)row * Nn;
        int cnt = 0;
        for (int base = 0; base < Nn; base += 32) {
            int j = base + lane;
            bool edge;
            if (mode == 1)      edge = r32[j] != 0;
            else if (mode == 2) edge = rf[j]  != 0.0f;
            else if (mode == 3) edge = rb[j]  != 0;
            else                edge = rd[j]  != 0.0;
            unsigned m = __ballot_sync(FULL, edge);
            if (edge) {
                int pos = cnt + __popc(m & ((1u << lane) - 1u));
                if (pos < MAXDEG) g_nbr[row * MAXDEG + pos] = j;
            }
            cnt += __popc(m);
        }
        if (lane == 0) g_deg[row] = (cnt < MAXDEG) ? cnt : MAXDEG;
    }
}

// ---------------- pack W1 [H,F,D] -> Bpack [F,H*D]; W2 [512,40] -> pad [512,64]
__global__ void k_pack(const float* __restrict__ W1, const float* __restrict__ W2) {
    int idx = blockIdx.x * 256 + threadIdx.x;
    if (idx < Hh * Ff * Dd) {
        int d = idx % Dd;
        int f = (idx / Dd) % Ff;
        int h = idx / (Dd * Ff);
        g_Bpack[(size_t)f * HD + h * Dd + d] = W1[idx];
    } else {
        int j = idx - Hh * Ff * Dd;   // over 512*64
        if (j < Ff * C2) {
            int c = j % C2;
            int k = j / C2;
            g_W2pad[j] = (c < Cc) ? W2[k * Cc + c] : 0.f;
        }
    }
}

// ---------------- TF32 tensor-core GEMM (3xTF32 error-compensated) -----------
__device__ __forceinline__ uint32_t f2tf(float x) {
    uint32_t r;
    asm("cvt.rna.tf32.f32 %0, %1;" : "=r"(r) : "f"(x));
    return r;
}

__device__ __forceinline__ void mma_tf32(float* c, uint32_t a0, uint32_t a1,
                                         uint32_t a2, uint32_t a3,
                                         uint32_t b0, uint32_t b1) {
    asm volatile(
        "mma.sync.aligned.m16n8k8.row.col.f32.tf32.tf32.f32 "
        "{%0,%1,%2,%3}, {%4,%5,%6,%7}, {%8,%9}, {%0,%1,%2,%3};"
        : "+f"(c[0]), "+f"(c[1]), "+f"(c[2]), "+f"(c[3])
        : "r"(a0), "r"(a1), "r"(a2), "r"(a3), "r"(b0), "r"(b1));
}

// C[M,Nc] = A[M,K] @ B[K,Nc], fp32 in/out, 3xTF32 internally.
// Block tile BM x BN, K-step 32, 256 threads, warp grid 4(M) x 2(N).
template <int BM, int BN>
__global__ __launch_bounds__(256) void k_gemm_tf32(
    const float* __restrict__ A, const float* __restrict__ B,
    float* __restrict__ Cm, int M, int K, int Nc)
{
    constexpr int WM = BM / 4;
    constexpr int WN = BN / 2;
    constexpr int MF = WM / 16;
    constexpr int NF = WN / 8;
    __shared__ float As[BM][36];        // [m][k], pad 36 for conflict-free frag ld
    __shared__ float Bs[32][BN + 8];    // [k][n], (BN+8)%32==8 -> conflict-free

    int t = threadIdx.x;
    int lane = t & 31, wid = t >> 5;
    int warpM = wid & 3, warpN = wid >> 2;
    int gId = lane >> 2, tig = lane & 3;
    int row0 = blockIdx.y * BM;
    int col0 = blockIdx.x * BN;

    float acc[MF][NF][4];
    #pragma unroll
    for (int i = 0; i < MF; i++)
        #pragma unroll
        for (int j = 0; j < NF; j++)
            #pragma unroll
            for (int q = 0; q < 4; q++) acc[i][j][q] = 0.f;

    for (int k0 = 0; k0 < K; k0 += 32) {
        // load A tile: BM x 32
        #pragma unroll
        for (int it = 0; it < BM / 32; it++) {
            int r = (t >> 3) + it * 32;
            int kb = (t & 7) * 4;
            float4 v = *(const float4*)&A[(size_t)(row0 + r) * K + k0 + kb];
            *(float4*)&As[r][kb] = v;
        }
        // load B tile: 32 x BN
        {
            constexpr int TPK = BN / 4;          // threads per k-row
            constexpr int RPI = 256 / TPK;       // k-rows per iter
            #pragma unroll
            for (int it = 0; it < 32 / RPI; it++) {
                int kr = t / TPK + it * RPI;
                int nb = (t % TPK) * 4;
                float4 v = *(const float4*)&B[(size_t)(k0 + kr) * Nc + col0 + nb];
                *(float4*)&Bs[kr][nb] = v;
            }
        }
        __syncthreads();

        #pragma unroll
        for (int ks = 0; ks < 4; ks++) {
            int kk = ks * 8;
            uint32_t ah[MF][4], al[MF][4];
            #pragma unroll
            for (int mf = 0; mf < MF; mf++) {
                int m0 = warpM * WM + mf * 16 + gId;
                float f0 = As[m0][kk + tig];
                float f1 = As[m0 + 8][kk + tig];
                float f2 = As[m0][kk + tig + 4];
                float f3 = As[m0 + 8][kk + tig + 4];
                ah[mf][0] = f2tf(f0); al[mf][0] = f2tf(f0 - __uint_as_float(ah[mf][0]));
                ah[mf][1] = f2tf(f1); al[mf][1] = f2tf(f1 - __uint_as_float(ah[mf][1]));
                ah[mf][2] = f2tf(f2); al[mf][2] = f2tf(f2 - __uint_as_float(ah[mf][2]));
                ah[mf][3] = f2tf(f3); al[mf][3] = f2tf(f3 - __uint_as_float(ah[mf][3]));
            }
            uint32_t bh[NF][2], bl[NF][2];
            #pragma unroll
            for (int nf = 0; nf < NF; nf++) {
                int n0 = warpN * WN + nf * 8 + gId;
                float f0 = Bs[kk + tig][n0];
                float f1 = Bs[kk + tig + 4][n0];
                bh[nf][0] = f2tf(f0); bl[nf][0] = f2tf(f0 - __uint_as_float(bh[nf][0]));
                bh[nf][1] = f2tf(f1); bl[nf][1] = f2tf(f1 - __uint_as_float(bh[nf][1]));
            }
            #pragma unroll
            for (int mf = 0; mf < MF; mf++)
                #pragma unroll
                for (int nf = 0; nf < NF; nf++) {
                    mma_tf32(acc[mf][nf], ah[mf][0], ah[mf][1], ah[mf][2], ah[mf][3],
                             bl[nf][0], bl[nf][1]);
                    mma_tf32(acc[mf][nf], al[mf][0], al[mf][1], al[mf][2], al[mf][3],
                             bh[nf][0], bh[nf][1]);
                    mma_tf32(acc[mf][nf], ah[mf][0], ah[mf][1], ah[mf][2], ah[mf][3],
                             bh[nf][0], bh[nf][1]);
                }
        }
        __syncthreads();
    }

    // epilogue
    #pragma unroll
    for (int mf = 0; mf < MF; mf++) {
        int r0 = row0 + warpM * WM + mf * 16 + gId;
        #pragma unroll
        for (int nf = 0; nf < NF; nf++) {
            int c0 = col0 + warpN * WN + nf * 8 + tig * 2;
            *(float2*)&Cm[(size_t)r0 * Nc + c0] = make_float2(acc[mf][nf][0], acc[mf][nf][1]);
            *(float2*)&Cm[(size_t)(r0 + 8) * Nc + c0] = make_float2(acc[mf][nf][2], acc[mf][nf][3]);
        }
    }
}

// ---------------- si/sj: per (n,h) dot with attention vectors ----------------
__global__ __launch_bounds__(256) void k_sisj(
    const float* __restrict__ a1_src, const float* __restrict__ a1_dst)
{
    __shared__ float ssrc[HD], sdst[HD];
    for (int i = threadIdx.x; i < HD; i += 256) { ssrc[i] = a1_src[i]; sdst[i] = a1_dst[i]; }
    __syncthreads();
    int t = threadIdx.x;
    int h = t & 7;
    int n = blockIdx.x * 32 + (t >> 3);
    const float* hp = &g_h[(size_t)n * HD + h * Dd];
    float si = 0.f, sj = 0.f;
    #pragma unroll 8
    for (int d = 0; d < Dd; d++) {
        float v = hp[d];
        si += v * sdst[h * Dd + d];
        sj += v * ssrc[h * Dd + d];
    }
    g_si[h * Nn + n] = si;
    g_sj[h * Nn + n] = sj;
}

// ---------------- layer-1 sparse attention + aggregate + ELU -----------------
__global__ __launch_bounds__(256) void k_layer1() {
    __shared__ int   nbr_sh[MAXDEG];
    __shared__ float w_sh[Hh][MAXDEG];
    int i = blockIdx.x;
    int deg = g_deg[i];
    int t = threadIdx.x, lane = t & 31, wid = t >> 5;
    for (int jj = t; jj < deg; jj += 256) nbr_sh[jj] = g_nbr[i * MAXDEG + jj];
    __syncthreads();

    // warp `wid` handles head `wid`: masked softmax over neighbors
    {
        int h = wid;
        float sii = g_si[h * Nn + i];
        float ev[4];
        float m = -1e30f;
        #pragma unroll
        for (int it = 0; it < 4; it++) {
            int jj = it * 32 + lane;
            float e = -1e30f;
            if (jj < deg) {
                float x = sii + g_sj[h * Nn + nbr_sh[jj]];
                e = (x >= 0.f) ? x : 0.2f * x;
            }
            ev[it] = e;
            m = fmaxf(m, e);
        }
        #pragma unroll
        for (int o = 16; o; o >>= 1) m = fmaxf(m, __shfl_xor_sync(0xffffffffu, m, o));
        float s = 0.f;
        #pragma unroll
        for (int it = 0; it < 4; it++) {
            int jj = it * 32 + lane;
            float w = (jj < deg) ? expf(ev[it] - m) : 0.f;
            ev[it] = w;
            s += w;
        }
        #pragma unroll
        for (int o = 16; o; o >>= 1) s += __shfl_xor_sync(0xffffffffu, s, o);
        float inv = 1.f / s;
        #pragma unroll
        for (int it = 0; it < 4; it++) {
            int jj = it * 32 + lane;
            if (jj < deg) w_sh[h][jj] = ev[it] * inv;
        }
    }
    __syncthreads();

    // aggregate: 512 dims = 256 threads x float2; thread t's head = t>>5
    {
        int h = t >> 5;                // 2t/64
        float2 acc = make_float2(0.f, 0.f);
        const float* wrow = w_sh[h];
        #pragma unroll 4
        for (int jj = 0; jj < deg; jj++) {
            float w = wrow[jj];
            float2 v = *(const float2*)&g_h[(size_t)nbr_sh[jj] * HD + 2 * t];
            acc.x += w * v.x;
            acc.y += w * v.y;
        }
        float2 r;
        r.x = (acc.x > 0.f) ? acc.x : expm1f(acc.x);
        r.y = (acc.y > 0.f) ? acc.y : expm1f(acc.y);
        *(float2*)&g_x2[(size_t)i * HD + 2 * t] = r;
    }
}

// ---------------- s2i/s2j: warp per node, dot h2 row with a2 vectors ---------
__global__ __launch_bounds__(256) void k_s2(
    const float* __restrict__ a2_src, const float* __restrict__ a2_dst)
{
    int t = threadIdx.x, lane = t & 31, wid = t >> 5;
    int i = blockIdx.x * 8 + wid;
    const float* h2 = &g_h2p[(size_t)i * C2];
    float pi = h2[lane] * ((lane < Cc) ? a2_dst[lane] : 0.f);
    float pj = h2[lane] * ((lane < Cc) ? a2_src[lane] : 0.f);
    if (lane < 8) {
        pi += h2[32 + lane] * a2_dst[32 + lane];
        pj += h2[32 + lane] * a2_src[32 + lane];
    }
    #pragma unroll
    for (int o = 16; o; o >>= 1) {
        pi += __shfl_xor_sync(0xffffffffu, pi, o);
        pj += __shfl_xor_sync(0xffffffffu, pj, o);
    }
    if (lane == 0) { g_s2i[i] = pi; g_s2j[i] = pj; }
}

// ---------------- layer-2 sparse attention -> final output -------------------
__global__ __launch_bounds__(64) void k_layer2(float* __restrict__ out) {
    __shared__ int   nbr_sh[MAXDEG];
    __shared__ float w_sh[MAXDEG];
    int i = blockIdx.x, t = threadIdx.x, lane = t & 31;
    int deg = g_deg[i];
    for (int jj = t; jj < deg; jj += 64) nbr_sh[jj] = g_nbr[i * MAXDEG + jj];
    __syncthreads();
    if (t < 32) {
        float sii = g_s2i[i];
        float ev[4];
        float m = -1e30f;
        #pragma unroll
        for (int it = 0; it < 4; it++) {
            int jj = it * 32 + lane;
            float e = -1e30f;
            if (jj < deg) {
                float x = sii + g_s2j[nbr_sh[jj]];
                e = (x >= 0.f) ? x : 0.2f * x;
            }
            ev[it] = e;
            m = fmaxf(m, e);
        }
        #pragma unroll
        for (int o = 16; o; o >>= 1) m = fmaxf(m, __shfl_xor_sync(0xffffffffu, m, o));
        float s = 0.f;
        #pragma unroll
        for (int it = 0; it < 4; it++) {
            int jj = it * 32 + lane;
            float w = (jj < deg) ? expf(ev[it] - m) : 0.f;
            ev[it] = w;
            s += w;
        }
        #pragma unroll
        for (int o = 16; o; o >>= 1) s += __shfl_xor_sync(0xffffffffu, s, o);
        float inv = 1.f / s;
        #pragma unroll
        for (int it = 0; it < 4; it++) {
            int jj = it * 32 + lane;
            if (jj < deg) w_sh[jj] = ev[it] * inv;
        }
    }
    __syncthreads();
    if (t < Cc) {
        float acc = 0.f;
        for (int jj = 0; jj < deg; jj++)
            acc += w_sh[jj] * g_h2p[(size_t)nbr_sh[jj] * C2 + t];
        out[(size_t)i * Cc + t] = acc;
    }
}

// ---------------- launch -----------------------------------------------------
extern "C" void kernel_launch(void* const* d_in, const int* in_sizes, int n_in,
                              void* d_out, int out_size) {
    const float*         x      = (const float*)d_in[0];
    const unsigned char* adj    = (const unsigned char*)d_in[1];
    const float*         W1     = (const float*)d_in[2];
    const float*         a1_src = (const float*)d_in[3];
    const float*         a1_dst = (const float*)d_in[4];
    const float*         W2     = (const float*)d_in[5];
    const float*         a2_src = (const float*)d_in[6];
    const float*         a2_dst = (const float*)d_in[7];
    float* out = (float*)d_out;

    static float* h_ptr = nullptr;
    static float* bpack_ptr = nullptr;
    static float* w2pad_ptr = nullptr;
    static float* x2_ptr = nullptr;
    static float* h2p_ptr = nullptr;
    if (!h_ptr) {
        cudaGetSymbolAddress((void**)&h_ptr, g_h);
        cudaGetSymbolAddress((void**)&bpack_ptr, g_Bpack);
        cudaGetSymbolAddress((void**)&w2pad_ptr, g_W2pad);
        cudaGetSymbolAddress((void**)&x2_ptr, g_x2);
        cudaGetSymbolAddress((void**)&h2p_ptr, g_h2p);
    }

    k_build<<<Nn / 8, 256>>>(adj);
    k_pack<<<(Hh * Ff * Dd + Ff * C2 + 255) / 256, 256>>>(W1, W2);
    k_gemm_tf32<128, 128><<<dim3(HD / 128, Nn / 128), 256>>>(x, bpack_ptr, h_ptr, Nn, Ff, HD);
    k_sisj<<<Nn / 32, 256>>>(a1_src, a1_dst);
    k_layer1<<<Nn, 256>>>();
    k_gemm_tf32<64, 64><<<dim3(C2 / 64, Nn / 64), 256>>>(x2_ptr, w2pad_ptr, h2p_ptr, Nn, HD, C2);
    k_s2<<<Nn / 8, 256>>>(a2_src, a2_dst);
    k_layer2<<<Nn, 64>>>(out);
}

// round 4
// speedup vs baseline: 1.2859x; 1.0841x over previous
#include <cuda_runtime.h>
#include <cuda_bf16.h>
#include <math.h>
#include <stdint.h>

#define Nn 4096
#define Ff 512
#define Dd 64
#define Hh 8
#define HD 512   // Hh*Dd
#define Cc 40
#define C2 64    // padded class dim
#define MAXDEG 128

// ---------------- scratch (static device globals; no allocation) -------------
__device__ int   g_deg[Nn];
__device__ int   g_nbr[Nn * MAXDEG];
__device__ float g_B1hi[Ff * HD];          // W1 repacked [F][H*D], tf32 hi
__device__ float g_B1lo[Ff * HD];          // tf32 lo residual
__device__ float g_B2hi[Ff * C2];          // W2 zero-padded [512][64], tf32 hi
__device__ float g_B2lo[Ff * C2];
__device__ float g_h[(size_t)Nn * HD];     // layer1 features, [n][h*D+d]
__device__ float g_si[Hh * Nn];
__device__ float g_sj[Hh * Nn];
__device__ float g_x2[(size_t)Nn * HD];
__device__ float g_h2p[(size_t)Nn * C2];   // padded h2
__device__ float g_s2i[Nn];
__device__ float g_s2j[Nn];

// ---------------- helpers ----------------------------------------------------
__device__ __forceinline__ uint32_t f2tf(float x) {
    uint32_t r;
    asm("cvt.rna.tf32.f32 %0, %1;" : "=r"(r) : "f"(x));
    return r;
}

__device__ __forceinline__ int detect_mode(const unsigned char* adj) {
    // adj[1][1] == 1 guaranteed (self loops)
    if (adj[(size_t)Nn + 1] == 1) return 0;                               // u8
    if (((const uint16_t*)adj)[(size_t)Nn + 1] == 0x3F80u) return 3;      // bf16
    uint32_t v32 = ((const uint32_t*)adj)[(size_t)Nn + 1];
    if (v32 == 0x3F800000u) return 2;                                     // f32
    if (((const uint64_t*)adj)[(size_t)Nn + 1] == 0x3FF0000000000000ull) return 4; // f64
    return 1;                                                             // i32
}

__device__ __forceinline__ unsigned nz4(unsigned w) {
    unsigned c = 0;
    if (w & 0x000000FFu) c |= 1u;
    if (w & 0x0000FF00u) c |= 2u;
    if (w & 0x00FF0000u) c |= 4u;
    if (w & 0xFF000000u) c |= 8u;
    return c;
}

// ---------------- build neighbor lists (1 warp per row, order-preserving) ----
__global__ __launch_bounds__(256) void k_build(const unsigned char* adj) {
    int row  = blockIdx.x * 8 + (threadIdx.x >> 5);
    int lane = threadIdx.x & 31;
    int mode = detect_mode(adj);
    const unsigned FULL = 0xffffffffu;

    if (mode == 0) {
        const uint4* r = (const uint4*)(adj + (size_t)row * Nn);
        int cnt = 0;
        #pragma unroll
        for (int it = 0; it < Nn / 512; it++) {
            uint4 v = r[it * 32 + lane];
            unsigned msk = nz4(v.x) | (nz4(v.y) << 4) | (nz4(v.z) << 8) | (nz4(v.w) << 12);
            int c = __popc(msk);
            int pref = c;
            #pragma unroll
            for (int o = 1; o < 32; o <<= 1) {
                int n = __shfl_up_sync(FULL, pref, o);
                if (lane >= o) pref += n;
            }
            int base = cnt + pref - c;
            int j0 = it * 512 + lane * 16;
            int pos = base;
            while (msk) {
                int b = __ffs(msk) - 1;
                msk &= msk - 1;
                if (pos < MAXDEG) g_nbr[row * MAXDEG + pos] = j0 + b;
                pos++;
            }
            cnt += __shfl_sync(FULL, pref, 31);
        }
        if (lane == 0) g_deg[row] = (cnt < MAXDEG) ? cnt : MAXDEG;
    } else {
        const int*      r32 = (const int*)adj + (size_t)row * Nn;
        const float*    rf  = (const float*)adj + (size_t)row * Nn;
        const uint16_t* rb  = (const uint16_t*)adj + (size_t)row * Nn;
        const double*   rd  = (const double*)adj + (size_t)row * Nn;
        int cnt = 0;
        for (int base = 0; base < Nn; base += 32) {
            int j = base + lane;
            bool edge;
            if (mode == 1)      edge = r32[j] != 0;
            else if (mode == 2) edge = rf[j]  != 0.0f;
            else if (mode == 3) edge = rb[j]  != 0;
            else                edge = rd[j]  != 0.0;
            unsigned m = __ballot_sync(FULL, edge);
            if (edge) {
                int pos = cnt + __popc(m & ((1u << lane) - 1u));
                if (pos < MAXDEG) g_nbr[row * MAXDEG + pos] = j;
            }
            cnt += __popc(m);
        }
        if (lane == 0) g_deg[row] = (cnt < MAXDEG) ? cnt : MAXDEG;
    }
}

// -------- pack + tf32-split W1 [H,F,D] -> [F,H*D], W2 [512,40] -> [512,64] ---
__global__ void k_pack(const float* __restrict__ W1, const float* __restrict__ W2) {
    int idx = blockIdx.x * 256 + threadIdx.x;
    if (idx < Hh * Ff * Dd) {
        int d = idx % Dd;
        int f = (idx / Dd) % Ff;
        int h = idx / (Dd * Ff);
        float v = W1[idx];
        float hi = __uint_as_float(f2tf(v));
        g_B1hi[(size_t)f * HD + h * Dd + d] = hi;
        g_B1lo[(size_t)f * HD + h * Dd + d] = __uint_as_float(f2tf(v - hi));
    } else {
        int j = idx - Hh * Ff * Dd;   // over 512*64
        if (j < Ff * C2) {
            int c = j % C2;
            int k = j / C2;
            float v = (c < Cc) ? W2[k * Cc + c] : 0.f;
            float hi = __uint_as_float(f2tf(v));
            g_B2hi[j] = hi;
            g_B2lo[j] = __uint_as_float(f2tf(v - hi));
        }
    }
}

// ---------------- TF32 tensor-core GEMM (3xTF32, B pre-split) ----------------
__device__ __forceinline__ void mma_tf32(float* c, uint32_t a0, uint32_t a1,
                                         uint32_t a2, uint32_t a3,
                                         uint32_t b0, uint32_t b1) {
    asm volatile(
        "mma.sync.aligned.m16n8k8.row.col.f32.tf32.tf32.f32 "
        "{%0,%1,%2,%3}, {%4,%5,%6,%7}, {%8,%9}, {%0,%1,%2,%3};"
        : "+f"(c[0]), "+f"(c[1]), "+f"(c[2]), "+f"(c[3])
        : "r"(a0), "r"(a1), "r"(a2), "r"(a3), "r"(b0), "r"(b1));
}

// C[M,Nc] = A[M,K] @ B[K,Nc]; A fp32 (split in-kernel), B pre-split hi/lo.
// 256 threads, warps 4(M) x 2(N). If FUSE_S2: also emit s2i/s2j per row
// (requires BN == Nc == C2; grid.x == 1).
template <int BM, int BN, bool FUSE_S2>
__global__ __launch_bounds__(256) void k_gemm_tf32(
    const float* __restrict__ A, const float* __restrict__ Bh,
    const float* __restrict__ Bl, float* __restrict__ Cm,
    int M, int K, int Nc,
    const float* __restrict__ a2_src, const float* __restrict__ a2_dst)
{
    constexpr int WM = BM / 4;
    constexpr int WN = BN / 2;
    constexpr int MF = WM / 16;
    constexpr int NF = WN / 8;
    __shared__ float As[BM][36];
    __shared__ float Bsh[32][BN + 8];
    __shared__ float Bsl[32][BN + 8];

    int t = threadIdx.x;
    int lane = t & 31, wid = t >> 5;
    int warpM = wid & 3, warpN = wid >> 2;
    int gId = lane >> 2, tig = lane & 3;
    int row0 = blockIdx.y * BM;
    int col0 = blockIdx.x * BN;

    float acc[MF][NF][4];
    #pragma unroll
    for (int i = 0; i < MF; i++)
        #pragma unroll
        for (int j = 0; j < NF; j++)
            #pragma unroll
            for (int q = 0; q < 4; q++) acc[i][j][q] = 0.f;

    for (int k0 = 0; k0 < K; k0 += 32) {
        #pragma unroll
        for (int it = 0; it < BM / 32; it++) {
            int r = (t >> 3) + it * 32;
            int kb = (t & 7) * 4;
            float4 v = *(const float4*)&A[(size_t)(row0 + r) * K + k0 + kb];
            *(float4*)&As[r][kb] = v;
        }
        {
            constexpr int TPK = BN / 4;
            constexpr int RPI = 256 / TPK;
            #pragma unroll
            for (int it = 0; it < 32 / RPI; it++) {
                int kr = t / TPK + it * RPI;
                int nb = (t % TPK) * 4;
                *(float4*)&Bsh[kr][nb] = *(const float4*)&Bh[(size_t)(k0 + kr) * Nc + col0 + nb];
                *(float4*)&Bsl[kr][nb] = *(const float4*)&Bl[(size_t)(k0 + kr) * Nc + col0 + nb];
            }
        }
        __syncthreads();

        #pragma unroll
        for (int ks = 0; ks < 4; ks++) {
            int kk = ks * 8;
            uint32_t ah[MF][4], al[MF][4];
            #pragma unroll
            for (int mf = 0; mf < MF; mf++) {
                int m0 = warpM * WM + mf * 16 + gId;
                float f0 = As[m0][kk + tig];
                float f1 = As[m0 + 8][kk + tig];
                float f2 = As[m0][kk + tig + 4];
                float f3 = As[m0 + 8][kk + tig + 4];
                ah[mf][0] = f2tf(f0); al[mf][0] = f2tf(f0 - __uint_as_float(ah[mf][0]));
                ah[mf][1] = f2tf(f1); al[mf][1] = f2tf(f1 - __uint_as_float(ah[mf][1]));
                ah[mf][2] = f2tf(f2); al[mf][2] = f2tf(f2 - __uint_as_float(ah[mf][2]));
                ah[mf][3] = f2tf(f3); al[mf][3] = f2tf(f3 - __uint_as_float(ah[mf][3]));
            }
            uint32_t bh[NF][2], bl[NF][2];
            #pragma unroll
            for (int nf = 0; nf < NF; nf++) {
                int n0 = warpN * WN + nf * 8 + gId;
                bh[nf][0] = __float_as_uint(Bsh[kk + tig][n0]);
                bh[nf][1] = __float_as_uint(Bsh[kk + tig + 4][n0]);
                bl[nf][0] = __float_as_uint(Bsl[kk + tig][n0]);
                bl[nf][1] = __float_as_uint(Bsl[kk + tig + 4][n0]);
            }
            #pragma unroll
            for (int mf = 0; mf < MF; mf++)
                #pragma unroll
                for (int nf = 0; nf < NF; nf++) {
                    mma_tf32(acc[mf][nf], ah[mf][0], ah[mf][1], ah[mf][2], ah[mf][3],
                             bl[nf][0], bl[nf][1]);
                    mma_tf32(acc[mf][nf], al[mf][0], al[mf][1], al[mf][2], al[mf][3],
                             bh[nf][0], bh[nf][1]);
                    mma_tf32(acc[mf][nf], ah[mf][0], ah[mf][1], ah[mf][2], ah[mf][3],
                             bh[nf][0], bh[nf][1]);
                }
        }
        __syncthreads();
    }

    #pragma unroll
    for (int mf = 0; mf < MF; mf++) {
        int r0 = row0 + warpM * WM + mf * 16 + gId;
        #pragma unroll
        for (int nf = 0; nf < NF; nf++) {
            int c0 = col0 + warpN * WN + nf * 8 + tig * 2;
            *(float2*)&Cm[(size_t)r0 * Nc + c0] = make_float2(acc[mf][nf][0], acc[mf][nf][1]);
            *(float2*)&Cm[(size_t)(r0 + 8) * Nc + c0] = make_float2(acc[mf][nf][2], acc[mf][nf][3]);
        }
    }

    if (FUSE_S2) {
        // BN == Nc == 64: this block holds complete rows of h2p.
        __syncthreads();   // make C writes visible block-wide
        float ad = (lane < Cc) ? a2_dst[lane] : 0.f;
        float as = (lane < Cc) ? a2_src[lane] : 0.f;
        float ad2 = (lane < Cc - 32) ? a2_dst[32 + lane] : 0.f;
        float as2 = (lane < Cc - 32) ? a2_src[32 + lane] : 0.f;
        #pragma unroll
        for (int r = 0; r < BM / 8; r++) {
            int row = row0 + wid * (BM / 8) + r;
            float2 v = make_float2(Cm[(size_t)row * Nc + lane],
                                   Cm[(size_t)row * Nc + 32 + lane]);
            float pi = v.x * ad + v.y * ad2;
            float pj = v.x * as + v.y * as2;
            #pragma unroll
            for (int o = 16; o; o >>= 1) {
                pi += __shfl_xor_sync(0xffffffffu, pi, o);
                pj += __shfl_xor_sync(0xffffffffu, pj, o);
            }
            if (lane == 0) { g_s2i[row] = pi; g_s2j[row] = pj; }
        }
    }
}

// ------------- si/sj: warp per node, fully coalesced row reads ---------------
__global__ __launch_bounds__(256) void k_sisj(
    const float* __restrict__ a1_src, const float* __restrict__ a1_dst)
{
    __shared__ float ssrc[HD], sdst[HD];
    for (int i = threadIdx.x; i < HD; i += 256) { ssrc[i] = a1_src[i]; sdst[i] = a1_dst[i]; }
    __syncthreads();
    int t = threadIdx.x, lane = t & 31, wid = t >> 5;
    int n = blockIdx.x * 8 + wid;
    #pragma unroll
    for (int it = 0; it < 4; it++) {
        float4 v = *(const float4*)&g_h[(size_t)n * HD + it * 128 + lane * 4];
        int head = it * 2 + (lane >> 4);
        int off = head * Dd + (lane & 15) * 4;
        float4 wd = *(const float4*)&sdst[off];
        float4 ws = *(const float4*)&ssrc[off];
        float si = v.x * wd.x + v.y * wd.y + v.z * wd.z + v.w * wd.w;
        float sj = v.x * ws.x + v.y * ws.y + v.z * ws.z + v.w * ws.w;
        #pragma unroll
        for (int o = 8; o; o >>= 1) {
            si += __shfl_xor_sync(0xffffffffu, si, o);
            sj += __shfl_xor_sync(0xffffffffu, sj, o);
        }
        if ((lane & 15) == 0) {
            g_si[head * Nn + n] = si;
            g_sj[head * Nn + n] = sj;
        }
    }
}

// ---------------- layer-1 sparse attention + aggregate + ELU -----------------
__global__ __launch_bounds__(256) void k_layer1() {
    __shared__ int   nbr_sh[MAXDEG];
    __shared__ float w_sh[Hh][MAXDEG];
    int i = blockIdx.x;
    int deg = g_deg[i];
    int t = threadIdx.x, lane = t & 31, wid = t >> 5;
    for (int jj = t; jj < deg; jj += 256) nbr_sh[jj] = g_nbr[i * MAXDEG + jj];
    __syncthreads();

    {
        int h = wid;
        float sii = g_si[h * Nn + i];
        float ev[4];
        float m = -1e30f;
        #pragma unroll
        for (int it = 0; it < 4; it++) {
            int jj = it * 32 + lane;
            float e = -1e30f;
            if (jj < deg) {
                float x = sii + g_sj[h * Nn + nbr_sh[jj]];
                e = (x >= 0.f) ? x : 0.2f * x;
            }
            ev[it] = e;
            m = fmaxf(m, e);
        }
        #pragma unroll
        for (int o = 16; o; o >>= 1) m = fmaxf(m, __shfl_xor_sync(0xffffffffu, m, o));
        float s = 0.f;
        #pragma unroll
        for (int it = 0; it < 4; it++) {
            int jj = it * 32 + lane;
            float w = (jj < deg) ? expf(ev[it] - m) : 0.f;
            ev[it] = w;
            s += w;
        }
        #pragma unroll
        for (int o = 16; o; o >>= 1) s += __shfl_xor_sync(0xffffffffu, s, o);
        float inv = 1.f / s;
        #pragma unroll
        for (int it = 0; it < 4; it++) {
            int jj = it * 32 + lane;
            if (jj < deg) w_sh[h][jj] = ev[it] * inv;
        }
    }
    __syncthreads();

    {
        int h = t >> 5;
        float2 acc = make_float2(0.f, 0.f);
        const float* wrow = w_sh[h];
        #pragma unroll 4
        for (int jj = 0; jj < deg; jj++) {
            float w = wrow[jj];
            float2 v = *(const float2*)&g_h[(size_t)nbr_sh[jj] * HD + 2 * t];
            acc.x += w * v.x;
            acc.y += w * v.y;
        }
        float2 r;
        r.x = (acc.x > 0.f) ? acc.x : expm1f(acc.x);
        r.y = (acc.y > 0.f) ? acc.y : expm1f(acc.y);
        *(float2*)&g_x2[(size_t)i * HD + 2 * t] = r;
    }
}

// ---------------- layer-2 sparse attention -> final output -------------------
__global__ __launch_bounds__(64) void k_layer2(float* __restrict__ out) {
    __shared__ int   nbr_sh[MAXDEG];
    __shared__ float w_sh[MAXDEG];
    int i = blockIdx.x, t = threadIdx.x, lane = t & 31;
    int deg = g_deg[i];
    for (int jj = t; jj < deg; jj += 64) nbr_sh[jj] = g_nbr[i * MAXDEG + jj];
    __syncthreads();
    if (t < 32) {
        float sii = g_s2i[i];
        float ev[4];
        float m = -1e30f;
        #pragma unroll
        for (int it = 0; it < 4; it++) {
            int jj = it * 32 + lane;
            float e = -1e30f;
            if (jj < deg) {
                float x = sii + g_s2j[nbr_sh[jj]];
                e = (x >= 0.f) ? x : 0.2f * x;
            }
            ev[it] = e;
            m = fmaxf(m, e);
        }
        #pragma unroll
        for (int o = 16; o; o >>= 1) m = fmaxf(m, __shfl_xor_sync(0xffffffffu, m, o));
        float s = 0.f;
        #pragma unroll
        for (int it = 0; it < 4; it++) {
            int jj = it * 32 + lane;
            float w = (jj < deg) ? expf(ev[it] - m) : 0.f;
            ev[it] = w;
            s += w;
        }
        #pragma unroll
        for (int o = 16; o; o >>= 1) s += __shfl_xor_sync(0xffffffffu, s, o);
        float inv = 1.f / s;
        #pragma unroll
        for (int it = 0; it < 4; it++) {
            int jj = it * 32 + lane;
            if (jj < deg) w_sh[jj] = ev[it] * inv;
        }
    }
    __syncthreads();
    if (t < Cc) {
        float acc = 0.f;
        for (int jj = 0; jj < deg; jj++)
            acc += w_sh[jj] * g_h2p[(size_t)nbr_sh[jj] * C2 + t];
        out[(size_t)i * Cc + t] = acc;
    }
}

// ---------------- launch -----------------------------------------------------
extern "C" void kernel_launch(void* const* d_in, const int* in_sizes, int n_in,
                              void* d_out, int out_size) {
    const float*         x      = (const float*)d_in[0];
    const unsigned char* adj    = (const unsigned char*)d_in[1];
    const float*         W1     = (const float*)d_in[2];
    const float*         a1_src = (const float*)d_in[3];
    const float*         a1_dst = (const float*)d_in[4];
    const float*         W2     = (const float*)d_in[5];
    const float*         a2_src = (const float*)d_in[6];
    const float*         a2_dst = (const float*)d_in[7];
    float* out = (float*)d_out;

    static float* h_ptr = nullptr;
    static float *b1h_ptr, *b1l_ptr, *b2h_ptr, *b2l_ptr, *x2_ptr, *h2p_ptr;
    if (!h_ptr) {
        cudaGetSymbolAddress((void**)&h_ptr, g_h);
        cudaGetSymbolAddress((void**)&b1h_ptr, g_B1hi);
        cudaGetSymbolAddress((void**)&b1l_ptr, g_B1lo);
        cudaGetSymbolAddress((void**)&b2h_ptr, g_B2hi);
        cudaGetSymbolAddress((void**)&b2l_ptr, g_B2lo);
        cudaGetSymbolAddress((void**)&x2_ptr, g_x2);
        cudaGetSymbolAddress((void**)&h2p_ptr, g_h2p);
    }

    k_build<<<Nn / 8, 256>>>(adj);
    k_pack<<<(Hh * Ff * Dd + Ff * C2 + 255) / 256, 256>>>(W1, W2);
    k_gemm_tf32<128, 64, false><<<dim3(HD / 64, Nn / 128), 256>>>(
        x, b1h_ptr, b1l_ptr, h_ptr, Nn, Ff, HD, nullptr, nullptr);
    k_sisj<<<Nn / 8, 256>>>(a1_src, a1_dst);
    k_layer1<<<Nn, 256>>>();
    k_gemm_tf32<64, 64, true><<<dim3(1, Nn / 64), 256>>>(
        x2_ptr, b2h_ptr, b2l_ptr, h2p_ptr, Nn, HD, C2, a2_src, a2_dst);
    k_layer2<<<Nn, 64>>>(out);
}

// round 5
// speedup vs baseline: 1.8767x; 1.4595x over previous
#include <cuda_runtime.h>
#include <cuda_bf16.h>
#include <math.h>
#include <stdint.h>

#define Nn 4096
#define Ff 512
#define Dd 64
#define Hh 8
#define HD 512   // Hh*Dd
#define Cc 40
#define C2 64    // padded class dim
#define MAXDEG 128

// ---------------- scratch (static device globals; no allocation) -------------
__device__ int   g_deg[Nn];
__device__ int   g_nbr[Nn * MAXDEG];
__device__ float g_h[(size_t)Nn * HD];     // layer1 features, [n][h*D+d]
__device__ float g_si[Hh * Nn];
__device__ float g_sj[Hh * Nn];
__device__ float g_x2[(size_t)Nn * HD];
__device__ float g_h2p[(size_t)Nn * C2];   // padded h2
__device__ float g_s2i[Nn];
__device__ float g_s2j[Nn];

// ---------------- helpers ----------------------------------------------------
__device__ __forceinline__ uint32_t f2tf(float x) {
    uint32_t r;
    asm("cvt.rna.tf32.f32 %0, %1;" : "=r"(r) : "f"(x));
    return r;
}

__device__ __forceinline__ void cp16(uint32_t dst_smem, const void* src) {
    asm volatile("cp.async.cg.shared.global [%0], [%1], 16;\n"
                 :: "r"(dst_smem), "l"(src) : "memory");
}
__device__ __forceinline__ void cp_commit() {
    asm volatile("cp.async.commit_group;\n" ::: "memory");
}
__device__ __forceinline__ void cp_wait1() {
    asm volatile("cp.async.wait_group 1;\n" ::: "memory");
}
__device__ __forceinline__ void cp_wait0() {
    asm volatile("cp.async.wait_group 0;\n" ::: "memory");
}

__device__ __forceinline__ int detect_mode(const unsigned char* adj) {
    // adj[1][1] == 1 guaranteed (self loops)
    if (adj[(size_t)Nn + 1] == 1) return 0;                               // u8
    if (((const uint16_t*)adj)[(size_t)Nn + 1] == 0x3F80u) return 3;      // bf16
    uint32_t v32 = ((const uint32_t*)adj)[(size_t)Nn + 1];
    if (v32 == 0x3F800000u) return 2;                                     // f32
    if (((const uint64_t*)adj)[(size_t)Nn + 1] == 0x3FF0000000000000ull) return 4; // f64
    return 1;                                                             // i32
}

__device__ __forceinline__ unsigned nz4(unsigned w) {
    unsigned c = 0;
    if (w & 0x000000FFu) c |= 1u;
    if (w & 0x0000FF00u) c |= 2u;
    if (w & 0x00FF0000u) c |= 4u;
    if (w & 0xFF000000u) c |= 8u;
    return c;
}

// emit compacted indices for a per-lane element mask; returns new count
__device__ __forceinline__ int emit_mask(int row, int cnt, unsigned msk,
                                         int j0, int lane) {
    const unsigned FULL = 0xffffffffu;
    int c = __popc(msk);
    int pref = c;
    #pragma unroll
    for (int o = 1; o < 32; o <<= 1) {
        int n = __shfl_up_sync(FULL, pref, o);
        if (lane >= o) pref += n;
    }
    int pos = cnt + pref - c;
    while (msk) {
        int b = __ffs(msk) - 1;
        msk &= msk - 1;
        if (pos < MAXDEG) g_nbr[row * MAXDEG + pos] = j0 + b;
        pos++;
    }
    return cnt + __shfl_sync(FULL, pref, 31);
}

// ---------------- build neighbor lists (1 warp per row, order-preserving) ----
__global__ __launch_bounds__(256) void k_build(const unsigned char* adj) {
    int row  = blockIdx.x * 8 + (threadIdx.x >> 5);
    int lane = threadIdx.x & 31;
    int mode = detect_mode(adj);
    int cnt = 0;

    if (mode == 0) {                        // u8: 16 elems / lane / iter
        const uint4* r = (const uint4*)(adj + (size_t)row * Nn);
        #pragma unroll
        for (int it = 0; it < Nn / 512; it++) {
            uint4 v = r[it * 32 + lane];
            unsigned msk = nz4(v.x) | (nz4(v.y) << 4) | (nz4(v.z) << 8) | (nz4(v.w) << 12);
            cnt = emit_mask(row, cnt, msk, it * 512 + lane * 16, lane);
        }
    } else if (mode == 1 || mode == 2) {    // i32/f32: 4 elems / lane / iter
        const uint4* r = (const uint4*)adj + (size_t)row * (Nn / 4);
        for (int it = 0; it < Nn / 128; it++) {
            uint4 v = r[it * 32 + lane];
            unsigned msk = (v.x ? 1u : 0u) | (v.y ? 2u : 0u) | (v.z ? 4u : 0u) | (v.w ? 8u : 0u);
            cnt = emit_mask(row, cnt, msk, it * 128 + lane * 4, lane);
        }
    } else if (mode == 3) {                 // bf16: 8 elems / lane / iter
        const uint4* r = (const uint4*)adj + (size_t)row * (Nn / 8);
        for (int it = 0; it < Nn / 256; it++) {
            uint4 v = r[it * 32 + lane];
            unsigned msk = 0;
            unsigned w[4] = {v.x, v.y, v.z, v.w};
            #pragma unroll
            for (int q = 0; q < 4; q++) {
                if (w[q] & 0x0000FFFFu) msk |= 1u << (2 * q);
                if (w[q] & 0xFFFF0000u) msk |= 2u << (2 * q);
            }
            cnt = emit_mask(row, cnt, msk, it * 256 + lane * 8, lane);
        }
    } else {                                // f64 scalar
        const double* rd = (const double*)adj + (size_t)row * Nn;
        const unsigned FULL = 0xffffffffu;
        for (int base = 0; base < Nn; base += 32) {
            int j = base + lane;
            bool edge = rd[j] != 0.0;
            unsigned m = __ballot_sync(FULL, edge);
            if (edge) {
                int pos = cnt + __popc(m & ((1u << lane) - 1u));
                if (pos < MAXDEG) g_nbr[row * MAXDEG + pos] = j;
            }
            cnt += __popc(m);
        }
    }
    if (lane == 0) g_deg[row] = (cnt < MAXDEG) ? cnt : MAXDEG;
}

// ------------- TF32 GEMM (3xTF32), cp.async double-buffered, fused row-dots --
__device__ __forceinline__ void mma_tf32(float* c, uint32_t a0, uint32_t a1,
                                         uint32_t a2, uint32_t a3,
                                         uint32_t b0, uint32_t b1) {
    asm volatile(
        "mma.sync.aligned.m16n8k8.row.col.f32.tf32.tf32.f32 "
        "{%0,%1,%2,%3}, {%4,%5,%6,%7}, {%8,%9}, {%0,%1,%2,%3};"
        : "+f"(c[0]), "+f"(c[1]), "+f"(c[2]), "+f"(c[3])
        : "r"(a0), "r"(a1), "r"(a2), "r"(a3), "r"(b0), "r"(b1));
}

// C[row0:row0+BM, col0:col0+64] = A @ B; K=512 fixed. B per-head slice of Bsrc,
// row length BCH*4 floats (64 for W1 slice, 40 for W2 -> zero-padded to 64).
// Epilogue: si_out[head*Nn+row] = C_row . avec_dst, sj_out likewise (cols < AVALID).
template <int BM, int BCH, int AVALID>
__global__ __launch_bounds__(256) void k_gemm(
    const float* __restrict__ A, const float* __restrict__ Bsrc,
    float* __restrict__ Cm, int Nc,
    const float* __restrict__ avec_src, const float* __restrict__ avec_dst,
    float* __restrict__ si_out, float* __restrict__ sj_out)
{
    constexpr int K = 512;
    constexpr int WM = BM / 4;
    constexpr int MF = WM / 16;
    constexpr int NF = 4;
    constexpr int BROW = BCH * 4;          // B global row length in floats

    extern __shared__ float sm[];
    float* As_   = sm;                      // [2][BM][36]
    float* Bs_   = sm + 2 * BM * 36;        // [2][32][72]
    float* s_siW = Bs_ + 2 * 32 * 72;       // [2][BM]
    float* s_sjW = s_siW + 2 * BM;          // [2][BM]
    uint32_t smb = (uint32_t)__cvta_generic_to_shared(sm);
    uint32_t asb = smb;
    uint32_t bsb = smb + 2 * BM * 36 * 4;

    int t = threadIdx.x, lane = t & 31, wid = t >> 5;
    int warpM = wid & 3, warpN = wid >> 2;
    int gId = lane >> 2, tig = lane & 3;
    int row0 = blockIdx.y * BM;
    int head = blockIdx.x;
    int col0 = head * 64;
    const float* Bp = Bsrc + (size_t)head * K * BROW;

    // zero pad columns of Bs once (only when B rows are short)
    if (BCH < 16 && t < 64) {
        float* rp = Bs_ + t * 72;
        #pragma unroll
        for (int c = BCH * 4; c < 72; c++) rp[c] = 0.f;
    }

    float acc[MF][NF][4];
    #pragma unroll
    for (int i = 0; i < MF; i++)
        #pragma unroll
        for (int j = 0; j < NF; j++)
            #pragma unroll
            for (int q = 0; q < 4; q++) acc[i][j][q] = 0.f;

    // prefetch helpers
    auto issue = [&](int stage, int k0) {
        #pragma unroll
        for (int it = 0; it < BM * 8 / 256; it++) {
            int id = t + it * 256;
            int r = id >> 3, c = id & 7;
            cp16(asb + ((stage * BM + r) * 36 + c * 4) * 4,
                 A + (size_t)(row0 + r) * K + k0 + c * 4);
        }
        constexpr int TOT = 32 * BCH;
        #pragma unroll
        for (int it = 0; it < (TOT + 255) / 256; it++) {
            int id = t + it * 256;
            if (id < TOT) {
                int r = id / BCH, c = id % BCH;
                cp16(bsb + ((stage * 32 + r) * 72 + c * 4) * 4,
                     Bp + (size_t)(k0 + r) * BROW + c * 4);
            }
        }
        cp_commit();
    };

    issue(0, 0);
    for (int kt = 0; kt < K / 32; kt++) {
        int cur = kt & 1;
        if (kt + 1 < K / 32) { issue(cur ^ 1, (kt + 1) * 32); cp_wait1(); }
        else cp_wait0();
        __syncthreads();

        const float* Asc = As_ + cur * BM * 36;
        const float* Bsc = Bs_ + cur * 32 * 72;
        #pragma unroll
        for (int ks = 0; ks < 4; ks++) {
            int kk = ks * 8;
            uint32_t ah[MF][4], al[MF][4];
            #pragma unroll
            for (int mf = 0; mf < MF; mf++) {
                int m0 = warpM * WM + mf * 16 + gId;
                float f0 = Asc[m0 * 36 + kk + tig];
                float f1 = Asc[(m0 + 8) * 36 + kk + tig];
                float f2 = Asc[m0 * 36 + kk + tig + 4];
                float f3 = Asc[(m0 + 8) * 36 + kk + tig + 4];
                ah[mf][0] = f2tf(f0); al[mf][0] = f2tf(f0 - __uint_as_float(ah[mf][0]));
                ah[mf][1] = f2tf(f1); al[mf][1] = f2tf(f1 - __uint_as_float(ah[mf][1]));
                ah[mf][2] = f2tf(f2); al[mf][2] = f2tf(f2 - __uint_as_float(ah[mf][2]));
                ah[mf][3] = f2tf(f3); al[mf][3] = f2tf(f3 - __uint_as_float(ah[mf][3]));
            }
            uint32_t bh[NF][2], bl[NF][2];
            #pragma unroll
            for (int nf = 0; nf < NF; nf++) {
                int n0 = warpN * 32 + nf * 8 + gId;
                float g0 = Bsc[(kk + tig) * 72 + n0];
                float g1 = Bsc[(kk + tig + 4) * 72 + n0];
                bh[nf][0] = f2tf(g0); bl[nf][0] = f2tf(g0 - __uint_as_float(bh[nf][0]));
                bh[nf][1] = f2tf(g1); bl[nf][1] = f2tf(g1 - __uint_as_float(bh[nf][1]));
            }
            #pragma unroll
            for (int mf = 0; mf < MF; mf++)
                #pragma unroll
                for (int nf = 0; nf < NF; nf++) {
                    mma_tf32(acc[mf][nf], ah[mf][0], ah[mf][1], ah[mf][2], ah[mf][3],
                             bl[nf][0], bl[nf][1]);
                    mma_tf32(acc[mf][nf], al[mf][0], al[mf][1], al[mf][2], al[mf][3],
                             bh[nf][0], bh[nf][1]);
                    mma_tf32(acc[mf][nf], ah[mf][0], ah[mf][1], ah[mf][2], ah[mf][3],
                             bh[nf][0], bh[nf][1]);
                }
        }
        __syncthreads();
    }

    // ---- C store ----
    #pragma unroll
    for (int mf = 0; mf < MF; mf++) {
        int r0 = row0 + warpM * WM + mf * 16 + gId;
        #pragma unroll
        for (int nf = 0; nf < NF; nf++) {
            int c0 = col0 + warpN * 32 + nf * 8 + tig * 2;
            *(float2*)&Cm[(size_t)r0 * Nc + c0] = make_float2(acc[mf][nf][0], acc[mf][nf][1]);
            *(float2*)&Cm[(size_t)(r0 + 8) * Nc + c0] = make_float2(acc[mf][nf][2], acc[mf][nf][3]);
        }
    }

    // ---- fused row dots: si/sj ----
    const unsigned FULL = 0xffffffffu;
    float advals[NF][2], asvals[NF][2];
    #pragma unroll
    for (int nf = 0; nf < NF; nf++) {
        int c = warpN * 32 + nf * 8 + tig * 2;
        advals[nf][0] = (c < AVALID) ? avec_dst[head * 64 + c] : 0.f;
        asvals[nf][0] = (c < AVALID) ? avec_src[head * 64 + c] : 0.f;
        advals[nf][1] = (c + 1 < AVALID) ? avec_dst[head * 64 + c + 1] : 0.f;
        asvals[nf][1] = (c + 1 < AVALID) ? avec_src[head * 64 + c + 1] : 0.f;
    }
    #pragma unroll
    for (int mf = 0; mf < MF; mf++) {
        float rAi = 0.f, rAj = 0.f, rBi = 0.f, rBj = 0.f;
        #pragma unroll
        for (int nf = 0; nf < NF; nf++) {
            rAi += acc[mf][nf][0] * advals[nf][0] + acc[mf][nf][1] * advals[nf][1];
            rAj += acc[mf][nf][0] * asvals[nf][0] + acc[mf][nf][1] * asvals[nf][1];
            rBi += acc[mf][nf][2] * advals[nf][0] + acc[mf][nf][3] * advals[nf][1];
            rBj += acc[mf][nf][2] * asvals[nf][0] + acc[mf][nf][3] * asvals[nf][1];
        }
        #pragma unroll
        for (int o = 1; o <= 2; o <<= 1) {
            rAi += __shfl_xor_sync(FULL, rAi, o);
            rAj += __shfl_xor_sync(FULL, rAj, o);
            rBi += __shfl_xor_sync(FULL, rBi, o);
            rBj += __shfl_xor_sync(FULL, rBj, o);
        }
        if (tig == 0) {
            int r = warpM * WM + mf * 16 + gId;
            s_siW[warpN * BM + r] = rAi;
            s_sjW[warpN * BM + r] = rAj;
            s_siW[warpN * BM + r + 8] = rBi;
            s_sjW[warpN * BM + r + 8] = rBj;
        }
    }
    __syncthreads();
    if (t < BM) {
        si_out[head * Nn + row0 + t] = s_siW[t] + s_siW[BM + t];
        sj_out[head * Nn + row0 + t] = s_sjW[t] + s_sjW[BM + t];
    }
}

// ---------------- layer-1 sparse attention + aggregate + ELU -----------------
__global__ __launch_bounds__(256) void k_layer1() {
    __shared__ int   nbr_sh[MAXDEG];
    __shared__ float w_sh[Hh][MAXDEG];
    int i = blockIdx.x;
    int deg = g_deg[i];
    int t = threadIdx.x, lane = t & 31, wid = t >> 5;
    for (int jj = t; jj < deg; jj += 256) nbr_sh[jj] = g_nbr[i * MAXDEG + jj];
    __syncthreads();

    {
        int h = wid;
        float sii = g_si[h * Nn + i];
        float ev[4];
        float m = -1e30f;
        #pragma unroll
        for (int it = 0; it < 4; it++) {
            int jj = it * 32 + lane;
            float e = -1e30f;
            if (jj < deg) {
                float x = sii + g_sj[h * Nn + nbr_sh[jj]];
                e = (x >= 0.f) ? x : 0.2f * x;
            }
            ev[it] = e;
            m = fmaxf(m, e);
        }
        #pragma unroll
        for (int o = 16; o; o >>= 1) m = fmaxf(m, __shfl_xor_sync(0xffffffffu, m, o));
        float s = 0.f;
        #pragma unroll
        for (int it = 0; it < 4; it++) {
            int jj = it * 32 + lane;
            float w = (jj < deg) ? expf(ev[it] - m) : 0.f;
            ev[it] = w;
            s += w;
        }
        #pragma unroll
        for (int o = 16; o; o >>= 1) s += __shfl_xor_sync(0xffffffffu, s, o);
        float inv = 1.f / s;
        #pragma unroll
        for (int it = 0; it < 4; it++) {
            int jj = it * 32 + lane;
            if (jj < deg) w_sh[h][jj] = ev[it] * inv;
        }
    }
    __syncthreads();

    {
        int h = t >> 5;
        float2 acc = make_float2(0.f, 0.f);
        const float* wrow = w_sh[h];
        #pragma unroll 4
        for (int jj = 0; jj < deg; jj++) {
            float w = wrow[jj];
            float2 v = *(const float2*)&g_h[(size_t)nbr_sh[jj] * HD + 2 * t];
            acc.x += w * v.x;
            acc.y += w * v.y;
        }
        float2 r;
        r.x = (acc.x > 0.f) ? acc.x : expm1f(acc.x);
        r.y = (acc.y > 0.f) ? acc.y : expm1f(acc.y);
        *(float2*)&g_x2[(size_t)i * HD + 2 * t] = r;
    }
}

// ---------------- layer-2 sparse attention -> final output -------------------
__global__ __launch_bounds__(64) void k_layer2(float* __restrict__ out) {
    __shared__ int   nbr_sh[MAXDEG];
    __shared__ float w_sh[MAXDEG];
    int i = blockIdx.x, t = threadIdx.x, lane = t & 31;
    int deg = g_deg[i];
    for (int jj = t; jj < deg; jj += 64) nbr_sh[jj] = g_nbr[i * MAXDEG + jj];
    __syncthreads();
    if (t < 32) {
        float sii = g_s2i[i];
        float ev[4];
        float m = -1e30f;
        #pragma unroll
        for (int it = 0; it < 4; it++) {
            int jj = it * 32 + lane;
            float e = -1e30f;
            if (jj < deg) {
                float x = sii + g_s2j[nbr_sh[jj]];
                e = (x >= 0.f) ? x : 0.2f * x;
            }
            ev[it] = e;
            m = fmaxf(m, e);
        }
        #pragma unroll
        for (int o = 16; o; o >>= 1) m = fmaxf(m, __shfl_xor_sync(0xffffffffu, m, o));
        float s = 0.f;
        #pragma unroll
        for (int it = 0; it < 4; it++) {
            int jj = it * 32 + lane;
            float w = (jj < deg) ? expf(ev[it] - m) : 0.f;
            ev[it] = w;
            s += w;
        }
        #pragma unroll
        for (int o = 16; o; o >>= 1) s += __shfl_xor_sync(0xffffffffu, s, o);
        float inv = 1.f / s;
        #pragma unroll
        for (int it = 0; it < 4; it++) {
            int jj = it * 32 + lane;
            if (jj < deg) w_sh[jj] = ev[it] * inv;
        }
    }
    __syncthreads();
    if (t < Cc) {
        float acc = 0.f;
        for (int jj = 0; jj < deg; jj++)
            acc += w_sh[jj] * g_h2p[(size_t)nbr_sh[jj] * C2 + t];
        out[(size_t)i * Cc + t] = acc;
    }
}

// ---------------- launch -----------------------------------------------------
#define SMEM_G1 ((2 * 128 * 36 + 2 * 32 * 72 + 4 * 128) * 4)   // 57344
#define SMEM_G2 ((2 * 64 * 36 + 2 * 32 * 72 + 4 * 64) * 4)     // 37888

extern "C" void kernel_launch(void* const* d_in, const int* in_sizes, int n_in,
                              void* d_out, int out_size) {
    const float*         x      = (const float*)d_in[0];
    const unsigned char* adj    = (const unsigned char*)d_in[1];
    const float*         W1     = (const float*)d_in[2];
    const float*         a1_src = (const float*)d_in[3];
    const float*         a1_dst = (const float*)d_in[4];
    const float*         W2     = (const float*)d_in[5];
    const float*         a2_src = (const float*)d_in[6];
    const float*         a2_dst = (const float*)d_in[7];
    float* out = (float*)d_out;

    static float *h_ptr = nullptr, *x2_ptr, *h2p_ptr, *si_ptr, *sj_ptr, *s2i_ptr, *s2j_ptr;
    if (!h_ptr) {
        cudaGetSymbolAddress((void**)&h_ptr, g_h);
        cudaGetSymbolAddress((void**)&x2_ptr, g_x2);
        cudaGetSymbolAddress((void**)&h2p_ptr, g_h2p);
        cudaGetSymbolAddress((void**)&si_ptr, g_si);
        cudaGetSymbolAddress((void**)&sj_ptr, g_sj);
        cudaGetSymbolAddress((void**)&s2i_ptr, g_s2i);
        cudaGetSymbolAddress((void**)&s2j_ptr, g_s2j);
        cudaFuncSetAttribute(k_gemm<128, 16, 64>,
                             cudaFuncAttributeMaxDynamicSharedMemorySize, SMEM_G1);
        cudaFuncSetAttribute(k_gemm<64, 10, Cc>,
                             cudaFuncAttributeMaxDynamicSharedMemorySize, SMEM_G2);
    }

    k_build<<<Nn / 8, 256>>>(adj);
    // layer-1 GEMM: C=g_h [4096,512]; B = W1 head slices; fused si/sj
    k_gemm<128, 16, 64><<<dim3(Hh, Nn / 128), 256, SMEM_G1>>>(
        x, W1, h_ptr, HD, a1_src, a1_dst, si_ptr, sj_ptr);
    k_layer1<<<Nn, 256>>>();
    // layer-2 GEMM: C=g_h2p [4096,64]; B = W2 (40-wide, zero-padded); fused s2
    k_gemm<64, 10, Cc><<<dim3(1, Nn / 64), 256, SMEM_G2>>>(
        x2_ptr, W2, h2p_ptr, C2, a2_src, a2_dst, s2i_ptr, s2j_ptr);
    k_layer2<<<Nn, 64>>>(out);
}